// round 1
// baseline (speedup 1.0000x reference)
#include <cuda_runtime.h>
#include <cuda_bf16.h>

#define BATCH 64
#define NPTS 1024
#define CHUNKS 8
#define JCHUNK (NPTS / CHUNKS)   // 128 j-values per block

// Deterministic scratch (no atomics, no allocations).
__device__ float g_partial[CHUNKS][BATCH][NPTS];  // 2 MB
__device__ float g_min[BATCH];

// ---------------------------------------------------------------------------
// Kernel 1: partial shift sums.
// Grid: (CHUNKS, BATCH), 1024 threads (one per shift s).
// shift_sum[b][s] += sum_{j in chunk} || x[b][j] - target[b][(j - s) mod N] ||
// Target is duplicated (2N float2) in smem so (j-s) mod N == linear index j-s+N.
// ---------------------------------------------------------------------------
__global__ void __launch_bounds__(1024, 2)
snake_main_kernel(const float2* __restrict__ x, const float2* __restrict__ tg)
{
    __shared__ float2 tdup[2 * NPTS];   // 16 KB
    __shared__ float2 xs[JCHUNK];       // 1 KB

    const int b     = blockIdx.y;
    const int chunk = blockIdx.x;
    const int j0    = chunk * JCHUNK;
    const int s     = threadIdx.x;      // shift handled by this thread

    const float2* __restrict__ tb = tg + b * NPTS;
    const float2* __restrict__ xb = x  + b * NPTS;

    // Fill duplicated target and x chunk.
    float2 tv0 = tb[s];
    tdup[s]        = tv0;
    tdup[s + NPTS] = tv0;
    if (s < JCHUNK) xs[s] = xb[j0 + s];
    __syncthreads();

    // Hot loop: linear smem addressing, no modulo, no index ALU beyond +1.
    float acc = 0.0f;
    const int base = j0 + NPTS - s;     // in [1, 2047-127]
    #pragma unroll 8
    for (int jj = 0; jj < JCHUNK; ++jj) {
        float2 xv = xs[jj];             // warp-uniform broadcast LDS
        float2 tv = tdup[base + jj];    // coalesced, conflict-free LDS
        float dx = xv.x - tv.x;
        float dy = xv.y - tv.y;
        float d2 = fmaf(dx, dx, dy * dy);
        float d;
        asm("sqrt.approx.f32 %0, %1;" : "=f"(d) : "f"(d2));  // 1 MUFU op
        acc += d;
    }

    g_partial[chunk][b][s] = acc;       // deterministic: unique slot per thread
}

// ---------------------------------------------------------------------------
// Kernel 2: per-batch reduce. Grid: (BATCH), 1024 threads.
// sum partials over chunks, then block-min over the 1024 shifts.
// Fixed-tree shuffle reduction -> deterministic.
// ---------------------------------------------------------------------------
__global__ void __launch_bounds__(1024)
snake_reduce_kernel(void)
{
    const int b = blockIdx.x;
    const int s = threadIdx.x;

    float sum = 0.0f;
    #pragma unroll
    for (int c = 0; c < CHUNKS; ++c)
        sum += g_partial[c][b][s];

    // warp min
    float v = sum;
    #pragma unroll
    for (int o = 16; o > 0; o >>= 1)
        v = fminf(v, __shfl_xor_sync(0xFFFFFFFFu, v, o));

    __shared__ float warpmin[32];
    if ((threadIdx.x & 31) == 0) warpmin[threadIdx.x >> 5] = v;
    __syncthreads();

    if (threadIdx.x < 32) {
        v = warpmin[threadIdx.x];
        #pragma unroll
        for (int o = 16; o > 0; o >>= 1)
            v = fminf(v, __shfl_xor_sync(0xFFFFFFFFu, v, o));
        if (threadIdx.x == 0) g_min[b] = v;   // min of raw sums; /N folded later
    }
}

// ---------------------------------------------------------------------------
// Kernel 3: final mean over batch. 1 block, 32 threads.
// out = (sum_b min_b) / (BATCH * NPTS)
// ---------------------------------------------------------------------------
__global__ void snake_final_kernel(float* __restrict__ out)
{
    float v = g_min[threadIdx.x] + g_min[threadIdx.x + 32];
    #pragma unroll
    for (int o = 16; o > 0; o >>= 1)
        v += __shfl_xor_sync(0xFFFFFFFFu, v, o);
    if (threadIdx.x == 0)
        out[0] = v * (1.0f / (float)(BATCH * NPTS));
}

// ---------------------------------------------------------------------------
extern "C" void kernel_launch(void* const* d_in, const int* in_sizes, int n_in,
                              void* d_out, int out_size)
{
    const float2* x  = (const float2*)d_in[0];
    const float2* tg = (const float2*)d_in[1];
    float* out = (float*)d_out;

    dim3 grid(CHUNKS, BATCH);
    snake_main_kernel<<<grid, 1024>>>(x, tg);
    snake_reduce_kernel<<<BATCH, 1024>>>();
    snake_final_kernel<<<1, 32>>>(out);
}

// round 2
// speedup vs baseline: 1.1313x; 1.1313x over previous
#include <cuda_runtime.h>
#include <cuda_bf16.h>

#define BATCH  64
#define NPTS   1024
#define CHUNKS 16
#define JCHUNK (NPTS / CHUNKS)   // 64 j-values per block
#define TPB    256               // threads per block; each owns 4 shifts
#define SPT    4                 // shifts per thread (TPB*SPT == NPTS)

// Deterministic scratch (no atomics, no allocations).
__device__ float g_partial[CHUNKS][BATCH][NPTS];  // 4 MB
__device__ float g_min[BATCH];

// ---- packed f32x2 helpers (ptxas will not auto-fuse; must be PTX) ----------
__device__ __forceinline__ unsigned long long pk2(float a, float b) {
    unsigned long long r;
    asm("mov.b64 %0, {%1, %2};" : "=l"(r) : "f"(a), "f"(b));
    return r;
}
__device__ __forceinline__ void upk2(unsigned long long v, float& a, float& b) {
    asm("mov.b64 {%0, %1}, %2;" : "=f"(a), "=f"(b) : "l"(v));
}
__device__ __forceinline__ unsigned long long addx2(unsigned long long a,
                                                    unsigned long long b) {
    unsigned long long r;
    asm("add.rn.f32x2 %0, %1, %2;" : "=l"(r) : "l"(a), "l"(b));
    return r;
}
__device__ __forceinline__ unsigned long long mulx2(unsigned long long a,
                                                    unsigned long long b) {
    unsigned long long r;
    asm("mul.rn.f32x2 %0, %1, %2;" : "=l"(r) : "l"(a), "l"(b));
    return r;
}
__device__ __forceinline__ float sqrt_approx(float x) {
    float r;
    asm("sqrt.approx.f32 %0, %1;" : "=f"(r) : "f"(x));
    return r;
}

// ---------------------------------------------------------------------------
// Kernel 1: partial shift sums.
// Grid: (CHUNKS, BATCH), TPB=256 threads; thread t owns shifts t, t+256, t+512, t+768.
// shift_sum[b][s] += sum_{j in chunk} || x[b][j] - target[b][(j - s) mod N] ||
// Target is duplicated (2N, pre-NEGATED) in smem: mod -> linear index, diff -> packed add.
// ---------------------------------------------------------------------------
__global__ void __launch_bounds__(TPB, 6)
snake_main_kernel(const float2* __restrict__ x, const float2* __restrict__ tg)
{
    __shared__ unsigned long long tdup[2 * NPTS];   // 16 KB, holds (-tx, -ty)
    __shared__ float4 xs4[JCHUNK / 2];              // 512 B, x points in pairs

    const int b     = blockIdx.y;
    const int chunk = blockIdx.x;
    const int j0    = chunk * JCHUNK;
    const int t     = threadIdx.x;

    const float2* __restrict__ tb = tg + b * NPTS;
    const float2* __restrict__ xb = x  + b * NPTS;

    // Fill duplicated negated target (4 points/thread) and x chunk pairs.
    #pragma unroll
    for (int i = t; i < NPTS; i += TPB) {
        float2 tv = tb[i];
        unsigned long long p = pk2(-tv.x, -tv.y);
        tdup[i]        = p;
        tdup[i + NPTS] = p;
    }
    if (t < JCHUNK / 2)
        xs4[t] = *(const float4*)(xb + j0 + 2 * t);
    __syncthreads();

    // tv index for shift s at offset jj: j0 + jj + NPTS - s  (always in [1, 2N-1])
    int base0 = j0 + NPTS - t;
    unsigned long long acc0 = 0, acc1 = 0, acc2 = 0, acc3 = 0;

    #pragma unroll 4
    for (int jj = 0; jj < JCHUNK; jj += 2) {
        float4 xq = xs4[jj >> 1];                    // LDS.128 broadcast: 2 points
        unsigned long long xv0 = pk2(xq.x, xq.y);
        unsigned long long xv1 = pk2(xq.z, xq.w);

        #pragma unroll
        for (int k = 0; k < SPT; ++k) {
            const int bs = base0 - k * TPB + jj;     // shift s = t + k*256
            unsigned long long t0 = tdup[bs];        // LDS.64, coalesced
            unsigned long long t1 = tdup[bs + 1];

            unsigned long long d0 = addx2(xv0, t0);  // (dx,dy) in one op
            unsigned long long d1 = addx2(xv1, t1);
            unsigned long long q0 = mulx2(d0, d0);   // (dx^2,dy^2)
            unsigned long long q1 = mulx2(d1, d1);

            float a0, b0f, a1, b1f;
            upk2(q0, a0, b0f);
            upk2(q1, a1, b1f);
            float r0 = sqrt_approx(a0 + b0f);
            float r1 = sqrt_approx(a1 + b1f);

            unsigned long long dpair = pk2(r0, r1);
            switch (k) {                              // packed accumulate
                case 0: acc0 = addx2(acc0, dpair); break;
                case 1: acc1 = addx2(acc1, dpair); break;
                case 2: acc2 = addx2(acc2, dpair); break;
                case 3: acc3 = addx2(acc3, dpair); break;
            }
        }
    }

    float lo, hi;
    upk2(acc0, lo, hi); g_partial[chunk][b][t          ] = lo + hi;
    upk2(acc1, lo, hi); g_partial[chunk][b][t + TPB    ] = lo + hi;
    upk2(acc2, lo, hi); g_partial[chunk][b][t + 2 * TPB] = lo + hi;
    upk2(acc3, lo, hi); g_partial[chunk][b][t + 3 * TPB] = lo + hi;
}

// ---------------------------------------------------------------------------
// Kernel 2: per-batch reduce. Grid: (BATCH), 1024 threads.
// Sum partials over chunks (fixed order), then block-min over the 1024 shifts.
// ---------------------------------------------------------------------------
__global__ void __launch_bounds__(1024)
snake_reduce_kernel(void)
{
    const int b = blockIdx.x;
    const int s = threadIdx.x;

    float sum = 0.0f;
    #pragma unroll
    for (int c = 0; c < CHUNKS; ++c)
        sum += g_partial[c][b][s];

    float v = sum;
    #pragma unroll
    for (int o = 16; o > 0; o >>= 1)
        v = fminf(v, __shfl_xor_sync(0xFFFFFFFFu, v, o));

    __shared__ float warpmin[32];
    if ((threadIdx.x & 31) == 0) warpmin[threadIdx.x >> 5] = v;
    __syncthreads();

    if (threadIdx.x < 32) {
        v = warpmin[threadIdx.x];
        #pragma unroll
        for (int o = 16; o > 0; o >>= 1)
            v = fminf(v, __shfl_xor_sync(0xFFFFFFFFu, v, o));
        if (threadIdx.x == 0) g_min[b] = v;   // min of raw sums; /N folded below
    }
}

// ---------------------------------------------------------------------------
// Kernel 3: final mean over batch. 1 block, 32 threads.
// ---------------------------------------------------------------------------
__global__ void snake_final_kernel(float* __restrict__ out)
{
    float v = g_min[threadIdx.x] + g_min[threadIdx.x + 32];
    #pragma unroll
    for (int o = 16; o > 0; o >>= 1)
        v += __shfl_xor_sync(0xFFFFFFFFu, v, o);
    if (threadIdx.x == 0)
        out[0] = v * (1.0f / (float)(BATCH * NPTS));
}

// ---------------------------------------------------------------------------
extern "C" void kernel_launch(void* const* d_in, const int* in_sizes, int n_in,
                              void* d_out, int out_size)
{
    const float2* x  = (const float2*)d_in[0];
    const float2* tg = (const float2*)d_in[1];
    float* out = (float*)d_out;

    dim3 grid(CHUNKS, BATCH);
    snake_main_kernel<<<grid, TPB>>>(x, tg);
    snake_reduce_kernel<<<BATCH, 1024>>>();
    snake_final_kernel<<<1, 32>>>(out);
}